// round 13
// baseline (speedup 1.0000x reference)
#include <cuda_runtime.h>
#include <cuda_bf16.h>

// Soft quantizer forward (levels = linspace(-2,2,25), uniform):
//   x_ste == x_hard == -2 + rint((x+2)*6)/6,  symbols = rint((x+2)*6).
//
// TERMINAL / CONVERGED (12 rounds; R9-R12 replicate at 16.86-17.15 us dur,
// sigma ~0.15 us). The straight-through estimator's forward value equals
// the hard quantization, so the softmax pipeline is dead code; uniform
// levels make the argmin closed-form (2 FMA + 2 FMNMX + 1 FRND/element).
// Remaining work is a mandatory 24 MB read + 72 MB write stream, pinned at
// the L2 write-path ceiling (~4.8 TB/s store side, ~6.4 TB/s blended).
// Eliminated levers: occupancy 38-73%, MLP 1-8/thread, grid 768-6144,
// block 256/512 (all flat); __stcs (+40% regression, slow L1tex
// evict-policy path); STG.128 is max ISA store width; TMA shares the
// path-independent LTS cap; output bytes are contractual.
// Shape: 1 float4/thread, exact-cover 3072x512 grid, 4x128-bit memory ops
// per thread, default cache policy.

__device__ __forceinline__ float4 quant_h(float4 v, float4* s) {
    const float STEP = 0.16666667f;   // 1/6
    float r0 = rintf(fminf(fmaxf(fmaf(v.x, 6.0f, 12.0f), 0.0f), 24.0f));
    float r1 = rintf(fminf(fmaxf(fmaf(v.y, 6.0f, 12.0f), 0.0f), 24.0f));
    float r2 = rintf(fminf(fmaxf(fmaf(v.z, 6.0f, 12.0f), 0.0f), 24.0f));
    float r3 = rintf(fminf(fmaxf(fmaf(v.w, 6.0f, 12.0f), 0.0f), 24.0f));
    *s = make_float4(r0, r1, r2, r3);
    return make_float4(fmaf(r0, STEP, -2.0f), fmaf(r1, STEP, -2.0f),
                       fmaf(r2, STEP, -2.0f), fmaf(r3, STEP, -2.0f));
}

// Exact-cover fast path: grid*block == n4, 3 output tensors, default stores.
__global__ void __launch_bounds__(512, 4)
softquant_exact(const float4* __restrict__ x4,
                float4* __restrict__ o0,
                float4* __restrict__ o1,
                float4* __restrict__ o2) {
    int i = blockIdx.x * 512 + threadIdx.x;
    float4 s4;
    float4 h4 = quant_h(x4[i], &s4);
    o0[i] = h4;      // x_ste (forward == x_hard)
    o1[i] = h4;      // x_hard
    o2[i] = s4;      // symbols (as float)
}

// Generic fallback for any other shape / output packing.
__global__ void __launch_bounds__(256)
softquant_generic(const float4* __restrict__ x4,
                  float4* __restrict__ o0,
                  float4* __restrict__ o1,
                  float4* __restrict__ o2,
                  int n4, int nblocks) {
    int i = blockIdx.x * blockDim.x + threadIdx.x;
    if (i >= n4) return;
    float4 s4;
    float4 h4 = quant_h(x4[i], &s4);
    o0[i] = h4;
    if (nblocks >= 2) o1[i] = h4;
    if (nblocks >= 3) o2[i] = s4;
}

extern "C" void kernel_launch(void* const* d_in, const int* in_sizes, int n_in,
                              void* d_out, int out_size) {
    const float* x = (const float*)d_in[0];
    float* out     = (float*)d_out;

    int n  = in_sizes[0];
    int n4 = n / 4;                     // 1,572,864 for the bench shape

    int nblocks = out_size / n;         // packed output tensors (expect 3)
    if (nblocks < 1) nblocks = 1;
    if (nblocks > 3) nblocks = 3;

    const float4* x4 = (const float4*)x;
    float4* o0 = (float4*)out;
    float4* o1 = (float4*)(out + (size_t)n);
    float4* o2 = (float4*)(out + 2 * (size_t)n);

    if ((n % 4 == 0) && (n4 % 512 == 0) && nblocks == 3) {
        softquant_exact<<<n4 / 512, 512>>>(x4, o0, o1, o2);   // 3072 blocks
    } else {
        int blocks = (n4 + 255) / 256;
        softquant_generic<<<blocks, 256>>>(x4, o0, o1, o2, n4, nblocks);
    }
}

// round 14
// speedup vs baseline: 1.0019x; 1.0019x over previous
#include <cuda_runtime.h>
#include <cuda_bf16.h>

// Soft quantizer forward (levels = linspace(-2,2,25), uniform):
//   x_ste == x_hard == -2 + rint((x+2)*6)/6,  symbols = rint((x+2)*6).
//
// TERMINAL / CONVERGED (13 rounds; R9-R13 replicate at 16.86-17.15 us dur,
// sigma ~0.15 us). The straight-through estimator's forward value equals
// the hard quantization, so the softmax pipeline is dead code; uniform
// levels make the argmin closed-form (2 FMA + 2 FMNMX + 1 FRND/element).
// Remaining work is a mandatory 24 MB read + 72 MB write stream, pinned at
// the L2 write-path ceiling (~4.8 TB/s store side, ~6.4 TB/s blended).
// Eliminated levers: occupancy 38-73%, MLP 1-8/thread, grid 768-6144,
// block 256/512 (all flat); __stcs (+40% regression, slow L1tex
// evict-policy path); STG.128 is max ISA store width; TMA shares the
// path-independent LTS cap; output bytes are contractual.
// Shape: 1 float4/thread, exact-cover 3072x512 grid, 4x128-bit memory ops
// per thread, default cache policy.

__device__ __forceinline__ float4 quant_h(float4 v, float4* s) {
    const float STEP = 0.16666667f;   // 1/6
    float r0 = rintf(fminf(fmaxf(fmaf(v.x, 6.0f, 12.0f), 0.0f), 24.0f));
    float r1 = rintf(fminf(fmaxf(fmaf(v.y, 6.0f, 12.0f), 0.0f), 24.0f));
    float r2 = rintf(fminf(fmaxf(fmaf(v.z, 6.0f, 12.0f), 0.0f), 24.0f));
    float r3 = rintf(fminf(fmaxf(fmaf(v.w, 6.0f, 12.0f), 0.0f), 24.0f));
    *s = make_float4(r0, r1, r2, r3);
    return make_float4(fmaf(r0, STEP, -2.0f), fmaf(r1, STEP, -2.0f),
                       fmaf(r2, STEP, -2.0f), fmaf(r3, STEP, -2.0f));
}

// Exact-cover fast path: grid*block == n4, 3 output tensors, default stores.
__global__ void __launch_bounds__(512, 4)
softquant_exact(const float4* __restrict__ x4,
                float4* __restrict__ o0,
                float4* __restrict__ o1,
                float4* __restrict__ o2) {
    int i = blockIdx.x * 512 + threadIdx.x;
    float4 s4;
    float4 h4 = quant_h(x4[i], &s4);
    o0[i] = h4;      // x_ste (forward == x_hard)
    o1[i] = h4;      // x_hard
    o2[i] = s4;      // symbols (as float)
}

// Generic fallback for any other shape / output packing.
__global__ void __launch_bounds__(256)
softquant_generic(const float4* __restrict__ x4,
                  float4* __restrict__ o0,
                  float4* __restrict__ o1,
                  float4* __restrict__ o2,
                  int n4, int nblocks) {
    int i = blockIdx.x * blockDim.x + threadIdx.x;
    if (i >= n4) return;
    float4 s4;
    float4 h4 = quant_h(x4[i], &s4);
    o0[i] = h4;
    if (nblocks >= 2) o1[i] = h4;
    if (nblocks >= 3) o2[i] = s4;
}

extern "C" void kernel_launch(void* const* d_in, const int* in_sizes, int n_in,
                              void* d_out, int out_size) {
    const float* x = (const float*)d_in[0];
    float* out     = (float*)d_out;

    int n  = in_sizes[0];
    int n4 = n / 4;                     // 1,572,864 for the bench shape

    int nblocks = out_size / n;         // packed output tensors (expect 3)
    if (nblocks < 1) nblocks = 1;
    if (nblocks > 3) nblocks = 3;

    const float4* x4 = (const float4*)x;
    float4* o0 = (float4*)out;
    float4* o1 = (float4*)(out + (size_t)n);
    float4* o2 = (float4*)(out + 2 * (size_t)n);

    if ((n % 4 == 0) && (n4 % 512 == 0) && nblocks == 3) {
        softquant_exact<<<n4 / 512, 512>>>(x4, o0, o1, o2);   // 3072 blocks
    } else {
        int blocks = (n4 + 255) / 256;
        softquant_generic<<<blocks, 256>>>(x4, o0, o1, o2, n4, nblocks);
    }
}